// round 16
// baseline (speedup 1.0000x reference)
#include <cuda_runtime.h>
#include <cstdint>

#define B_TOT   4096
#define NTOK    49
#define CDIM    128
#define TPB     256
#define SCALE   0.17677669529663687f   /* 32^-0.5 */
#define FULLM   0xffffffffu
#define NEG_INF (__int_as_float(0xff800000))

typedef unsigned long long u64;
typedef unsigned char u8;

// ---- packed f32x2 helpers (sm_100+ PTX) --------------------------------
static __device__ __forceinline__ void ffma2(u64& acc, u64 a, u64 b) {
    asm("fma.rn.f32x2 %0, %1, %2, %0;" : "+l"(acc) : "l"(a), "l"(b));
}
static __device__ __forceinline__ float2 unpackf2(u64 v) {
    float2 r;
    asm("mov.b64 {%0, %1}, %2;" : "=f"(r.x), "=f"(r.y) : "l"(v));
    return r;
}
static __device__ __forceinline__ u64 packf2(float x, float y) {
    u64 r;
    asm("mov.b64 %0, {%1, %2};" : "=l"(r) : "f"(x), "f"(y));
    return r;
}

// ---- shared memory (113,812 B -> 2 CTAs/SM) ----------------------------
// wbuf: W k-slice (16 k values = 4 k-quads), double-buffered.
//       float view: wf[k4l*516 + c*4 + (k&3)]
// xq  : row-major [49][128]; lifecycle: x -> q(in-place) -> attn-out -> proj-in
// ktp : k packed by d-PAIRS: u64 (k[m][2d],k[m][2d+1]) at [d2*51 + m]
// vp  : v packed by m-PAIRS: u64 (v[2m2][c],v[2m2+1][c]) at [m2*130 + c]
// pp  : per-warp prob rows: pp[wy*364 + r*52 + m] (pads m=49..51 zeroed)
struct Smem {
    ulonglong2 wbuf[2][4 * 129];           // 16512 B
    float xq[NTOK * CDIM];                 // 25088 B
    u64  ktp[64 * 51];                     // 26112 B
    u64  vp[25 * 130];                     // 26000 B
    float pp[8 * 7 * 52];                  // 11648 B
    u8    ridx8[2404];                     //  2404 B
    float rtab[169 * 4];                   //  2704 B
    float bqs[384];
    float pbs[CDIM];
    float invT[64];
    float uBs[64];
    float gts[4 * NTOK];
};
#define SMEM_BYTES ((int)sizeof(Smem))

// stage one 8KB W slice (k in [16s,16s+16)) of a 128x128 chunk into wbuf[buf]
static __device__ __forceinline__ void stage_slice(Smem* sm, int buf,
                                                   const float* __restrict__ wchunk,
                                                   int s, int tid) {
    float* wf = reinterpret_cast<float*>(sm->wbuf[buf]);
    const float4* s4 = reinterpret_cast<const float4*>(wchunk);
    #pragma unroll
    for (int i = 0; i < 2; i++) {
        int job = tid + i * TPB;          // job = c*4 + k4l
        int c   = job >> 2;
        int k4l = job & 3;
        float4 v = s4[c * 32 + s * 4 + k4l];
        *reinterpret_cast<float4*>(wf + k4l * 516 + c * 4) = v;
    }
}

// one 16-k slice of GEMM: NR rows x 128 cols, acc packed (lo=even k, hi=odd k)
template <int NR>
static __device__ __forceinline__ void gemm_slice(const Smem* sm, int buf, int k4base,
                                                  int n0, int lane, u64 (&acc)[7][4]) {
    const ulonglong2* wq = sm->wbuf[buf];
    const float4* xs = reinterpret_cast<const float4*>(sm->xq);
    #pragma unroll
    for (int k4l = 0; k4l < 4; k4l++) {
        ulonglong2 w0 = wq[k4l * 129 + lane];
        ulonglong2 w1 = wq[k4l * 129 + lane + 32];
        ulonglong2 w2 = wq[k4l * 129 + lane + 64];
        ulonglong2 w3 = wq[k4l * 129 + lane + 96];
        #pragma unroll
        for (int rr = 0; rr < NR; rr++) {
            float4 xv = xs[(n0 + rr) * 32 + k4base + k4l];   // 16B broadcast
            u64 xlo = packf2(xv.x, xv.y);
            u64 xhi = packf2(xv.z, xv.w);
            ffma2(acc[rr][0], xlo, w0.x);
            ffma2(acc[rr][1], xlo, w1.x);
            ffma2(acc[rr][2], xlo, w2.x);
            ffma2(acc[rr][3], xlo, w3.x);
            ffma2(acc[rr][0], xhi, w0.y);
            ffma2(acc[rr][1], xhi, w1.y);
            ffma2(acc[rr][2], xhi, w2.y);
            ffma2(acc[rr][3], xhi, w3.y);
        }
    }
}

// attention for (head h, row-group at n0); R rows; lanes = keys (QK) / dims (PV)
// q read from xq rows n0..n0+R-1 (own rows); output written in-place (head cols)
template <int R>
static __device__ __forceinline__ void attn_block(Smem* sm, int h, int n0,
                                                  int lane, int wy) {
    const int h16 = h * 16;
    const int hd0 = h * 32;
    const u64* ktu = sm->ktp;
    const u64* vpu = sm->vp;
    const float4* q4 = reinterpret_cast<const float4*>(sm->xq);
    float* ppw = sm->pp + wy * 364;

    // ---- QK: float4 q broadcast (4 dims/iter), K via LDS.64 ----
    u64 s0[R], s1[R];
    #pragma unroll
    for (int r = 0; r < R; r++) { s0[r] = 0ull; s1[r] = 0ull; }
    #pragma unroll 4
    for (int dd4 = 0; dd4 < 8; dd4++) {
        int d2a = h16 + 2 * dd4;
        u64 ka0 = ktu[d2a * 51 + lane];
        u64 ka1 = ktu[d2a * 51 + 32 + lane];        // hi lanes: dead values
        u64 kb0 = ktu[(d2a + 1) * 51 + lane];
        u64 kb1 = ktu[(d2a + 1) * 51 + 32 + lane];
        #pragma unroll
        for (int r = 0; r < R; r++) {
            float4 q = q4[(n0 + r) * 32 + h * 8 + dd4];   // 16B broadcast
            u64 qlo = packf2(q.x, q.y);
            u64 qhi = packf2(q.z, q.w);
            ffma2(s0[r], qlo, ka0);
            ffma2(s1[r], qlo, ka1);
            ffma2(s0[r], qhi, kb0);
            ffma2(s1[r], qhi, kb1);
        }
    }

    // ---- softmax (lanes = keys) ----
    float uB0 = sm->uBs[lane];
    float uB1 = (lane < 17) ? sm->uBs[lane + 32] : 0.f;
    #pragma unroll
    for (int r = 0; r < R; r++) {
        int n = n0 + r;
        float2 t0 = unpackf2(s0[r]);
        float2 t1 = unpackf2(s1[r]);
        float bias0 = sm->rtab[(int)sm->ridx8[n * NTOK + lane] * 4 + h] - uB0;
        float a0 = fmaf(t0.x + t0.y, SCALE, bias0);
        float a1 = NEG_INF;
        if (lane < 17) {
            float bias1 = sm->rtab[(int)sm->ridx8[n * NTOK + lane + 32] * 4 + h] - uB1;
            a1 = fmaf(t1.x + t1.y, SCALE, bias1);
        }
        float mx = fmaxf(a0, a1);
        #pragma unroll
        for (int o = 16; o > 0; o >>= 1) mx = fmaxf(mx, __shfl_xor_sync(FULLM, mx, o));
        float e0 = __expf(a0 - mx);
        float e1 = (lane < 17) ? __expf(a1 - mx) : 0.f;
        float smv = e0 + e1;
        #pragma unroll
        for (int o = 16; o > 0; o >>= 1) smv += __shfl_xor_sync(FULLM, smv, o);
        float inv = __fdividef(1.f, smv);
        ppw[r * 52 + lane] = e0 * inv;
        if (lane < 17)      ppw[r * 52 + 32 + lane] = e1 * inv;
        else if (lane < 20) ppw[r * 52 + 32 + lane] = 0.f;   // pads m=49..51
    }
    __syncwarp();

    // ---- PV: float4 prob broadcast; lanes = head dims ----
    const float4* pp4 = reinterpret_cast<const float4*>(ppw);   // [r*13 + m4]
    u64 o2[R];
    #pragma unroll
    for (int r = 0; r < R; r++) o2[r] = 0ull;
    #pragma unroll 4
    for (int m4 = 0; m4 < 12; m4++) {
        u64 v0 = vpu[(2 * m4) * 130 + hd0 + lane];
        u64 v1 = vpu[(2 * m4 + 1) * 130 + hd0 + lane];
        #pragma unroll
        for (int r = 0; r < R; r++) {
            float4 p = pp4[r * 13 + m4];               // 16B broadcast
            u64 plo = packf2(p.x, p.y);
            u64 phi = packf2(p.z, p.w);
            ffma2(o2[r], plo, v0);
            ffma2(o2[r], phi, v1);
        }
    }
    {   // tail m2 = 24 (keys 48,49; key 49 weight zero)
        const u64* ppu = reinterpret_cast<const u64*>(ppw);
        u64 v0 = vpu[24 * 130 + hd0 + lane];
        #pragma unroll
        for (int r = 0; r < R; r++) ffma2(o2[r], ppu[r * 26 + 24], v0);
    }

    // gated in-place write: xq[n][hd0+lane] (own rows, own head cols)
    #pragma unroll
    for (int r = 0; r < R; r++) {
        int n = n0 + r;
        float2 t = unpackf2(o2[r]);
        sm->xq[n * CDIM + hd0 + lane] = (t.x + t.y) * sm->gts[h * NTOK + n];
    }
    __syncwarp();   // pp reads done before next block overwrites
}

__global__ void __launch_bounds__(TPB, 2)
attn_win_kernel(const float* __restrict__ x,
                const float* __restrict__ ut,
                const float* __restrict__ ub,
                const float* __restrict__ gate,
                const float* __restrict__ qkv_w,
                const float* __restrict__ qkv_b,
                const float* __restrict__ proj_w,
                const float* __restrict__ proj_b,
                const float* __restrict__ rel_table,
                const int*   __restrict__ rel_index,
                float* __restrict__ out) {
    extern __shared__ char smem_raw[];
    Smem* sm = reinterpret_cast<Smem*>(smem_raw);
    float* ktpf = reinterpret_cast<float*>(sm->ktp);
    float* vpf  = reinterpret_cast<float*>(sm->vp);

    const int b    = blockIdx.x;
    const int tid  = threadIdx.x;
    const int lane = tid & 31;
    const int wy   = tid >> 5;

    // ---------------- init: constants, pads, x, first W slice --------
    for (int i = tid; i < NTOK * NTOK; i += TPB) sm->ridx8[i] = (u8)rel_index[i];
    for (int i = tid; i < 676; i += TPB) sm->rtab[i] = rel_table[i];
    for (int i = tid; i < 384; i += TPB) sm->bqs[i] = qkv_b[i];
    if (tid < CDIM) sm->pbs[tid] = proj_b[tid];
    for (int i = tid; i < 8 * 364; i += TPB) sm->pp[i] = 0.f;
    if (tid < 256) {                          // ktp pads m=49,50 per d2 row
        int d2 = tid >> 2, off = tid & 3;
        ktpf[d2 * 102 + 98 + off] = 0.f;
    }
    if (tid < 128) vpf[24 * 260 + 2 * tid + 1] = 0.f;   // vp pad row m=49
    if (tid < 64) { sm->invT[tid] = 0.f; sm->uBs[tid] = 0.f; }
    __syncthreads();
    if (tid < NTOK) {
        float t  = ut[b * NTOK + tid];
        float sg = 1.f / (1.f + __expf(-t));
        sm->invT[tid] = 1.f / (0.1f + 4.f * sg);
        float u = ub[b * NTOK + tid];
        sm->uBs[tid] = u > 0.f ? u : 0.f;
    }
    if (tid < 4 * NTOK) sm->gts[tid] = gate[(size_t)b * (4 * NTOK) + tid];
    {   // x -> xq (row-major float4 copy)
        const float4* x4 = reinterpret_cast<const float4*>(x + (size_t)b * (NTOK * CDIM));
        float4* xq4 = reinterpret_cast<float4*>(sm->xq);
        for (int i = tid; i < NTOK * 32; i += TPB) xq4[i] = x4[i];
    }
    // chunk order: v, k, q, proj
    const float* Wseq[4] = {qkv_w + 2 * 16384, qkv_w + 16384, qkv_w, proj_w};
    const int    bofs[4] = {256, 128, 0, 0};
    stage_slice(sm, 0, Wseq[0], 0, tid);
    __syncthreads();

    // row-group per warp (8 warps)
    const int rg = wy;
    const int n0 = (rg == 0) ? 0 : 6 * rg + 1;
    const int NRv = (rg == 0) ? 7 : 6;

    u64 acc[7][4];
    for (int t = 0; t < 32; t++) {
        const int jc = t >> 3, s = t & 7;
        if (s == 0) {
            #pragma unroll
            for (int rr = 0; rr < 7; rr++)
                #pragma unroll
                for (int cc = 0; cc < 4; cc++) acc[rr][cc] = 0ull;
        }
        if (t < 31) stage_slice(sm, (t + 1) & 1, Wseq[(t + 1) >> 3], (t + 1) & 7, tid);
        if (NRv == 7) gemm_slice<7>(sm, t & 1, 4 * s, n0, lane, acc);
        else          gemm_slice<6>(sm, t & 1, 4 * s, n0, lane, acc);
        __syncthreads();

        if (s == 7) {
            const float* bq = sm->bqs + bofs[jc];
            #pragma unroll
            for (int rr = 0; rr < 7; rr++) {
                if (rr < NRv) {
                    int n = n0 + rr;
                    #pragma unroll
                    for (int cc = 0; cc < 4; cc++) {
                        int c = 32 * cc + lane;
                        float2 sv = unpackf2(acc[rr][cc]);
                        float v = sv.x + sv.y;
                        if (jc == 0)      vpf[(n >> 1) * 260 + 2 * c + (n & 1)] = v + bq[c];
                        else if (jc == 1) ktpf[(c >> 1) * 102 + 2 * n + (c & 1)] = v + bq[c];
                        else if (jc == 2) sm->xq[n * CDIM + c] = (v + bq[c]) * sm->invT[n];
                        else out[(size_t)b * (NTOK * CDIM) + n * CDIM + c] = v + sm->pbs[c];
                    }
                }
            }
            if (jc == 2) {
                // attention: q-epilogue above was warp-local (own rows);
                // all attention smem traffic is own-rows / head-disjoint cols.
                #pragma unroll
                for (int h = 0; h < 4; h++) {
                    if (rg == 0) attn_block<7>(sm, h, 0, lane, wy);
                    else         attn_block<6>(sm, h, n0, lane, wy);
                }
                __syncthreads();   // proj gemm reads ALL xq rows
            }
        }
    }
}

extern "C" void kernel_launch(void* const* d_in, const int* in_sizes, int n_in,
                              void* d_out, int out_size) {
    const float* x      = (const float*)d_in[0];
    const float* ut     = (const float*)d_in[1];
    const float* ubias  = (const float*)d_in[2];
    const float* gate   = (const float*)d_in[3];
    const float* qkv_w  = (const float*)d_in[4];
    const float* qkv_b  = (const float*)d_in[5];
    const float* proj_w = (const float*)d_in[6];
    const float* proj_b = (const float*)d_in[7];
    const float* rtab   = (const float*)d_in[8];
    const int*   ridx   = (const int*)d_in[9];
    float* out = (float*)d_out;

    cudaFuncSetAttribute(attn_win_kernel,
                         cudaFuncAttributeMaxDynamicSharedMemorySize, SMEM_BYTES);
    attn_win_kernel<<<B_TOT, TPB, SMEM_BYTES>>>(
        x, ut, ubias, gate, qkv_w, qkv_b, proj_w, proj_b, rtab, ridx, out);
}